// round 10
// baseline (speedup 1.0000x reference)
#include <cuda_runtime.h>
#include <cuda_bf16.h>
#include <cstdint>

// Problem shape (fixed by reference)
#define PN 8
#define PH 32
#define PL 512
#define PS 512
#define PLS (PL * PS)
#define MAXP 100
#define TPAD 33           // pad: bank = (p + h) % 32, p random -> uniform

__global__ __launch_bounds__(256, 6)
void gpe_kernel(const float* __restrict__ QK,
                const int* __restrict__ pos,
                const float* __restrict__ table,
                float* __restrict__ out) {
    __shared__ float t_sh[MAXP * TPAD];  // t_sh[p*33 + h]

    const int bid = blockIdx.x;          // n*PL + l  (one (n,l) row per block)
    const int n = bid >> 9;
    const int l = bid & (PL - 1);
    const int tid = threadIdx.x;

    // Thread owns one s4 (4 consecutive s) and 16 CONTIGUOUS heads
    // (bursts of 8 consecutive heads -> LDG/STG offsets fold into immediates).
    const int s4 = tid & 127;
    const int hq = tid >> 7;             // 0 or 1 -> heads hq*16 .. hq*16+15

    // Issue pos load FIRST so it overlaps the table staging below.
    const int4 pp = __ldg(reinterpret_cast<const int4*>(
        pos + ((size_t)n * PL + l) * PS) + s4);

    // Stage table: 800 float4 covering [100][32] row-major; row 0 zeroed.
    const float4* table4 = reinterpret_cast<const float4*>(table);
    #pragma unroll
    for (int i = tid; i < (MAXP * PH) / 4; i += 256) {
        const int p  = i >> 3;
        const int h4 = (i & 7) << 2;
        float4 v = __ldg(table4 + i);
        if (p == 0) { v.x = 0.f; v.y = 0.f; v.z = 0.f; v.w = 0.f; }
        float* dst = &t_sh[p * TPAD + h4];
        dst[0] = v.x; dst[1] = v.y; dst[2] = v.z; dst[3] = v.w;
    }

    // Gather bases (addr = px + h, pure add in the hot loop)
    const int px = pp.x * TPAD;
    const int py = pp.y * TPAD;
    const int pz = pp.z * TPAD;
    const int pw = pp.w * TPAD;

    __syncthreads();

    const size_t base = ((size_t)n * PH + hq * 16) * (size_t)PLS
                      + (size_t)l * PS + ((size_t)s4 << 2);

    // Two bursts of 8 CONSECUTIVE heads. All 8 load (and store) addresses
    // are base + j*PLS (max 7.3 MB) -> single base reg + LDG immediates.
    #pragma unroll
    for (int half = 0; half < 2; half++) {
        const float* qk0 = QK  + base + (size_t)(half * 8) * PLS;
        float*       ot0 = out + base + (size_t)(half * 8) * PLS;

        float4 q[8];
        #pragma unroll
        for (int j = 0; j < 8; j++) {
            q[j] = __ldcs(reinterpret_cast<const float4*>(qk0 + (size_t)j * PLS));
        }

        const int hb = hq * 16 + half * 8;   // first head of this burst
        #pragma unroll
        for (int j = 0; j < 8; j++) {
            const int h = hb + j;
            q[j].x += t_sh[px + h];
            q[j].y += t_sh[py + h];
            q[j].z += t_sh[pz + h];
            q[j].w += t_sh[pw + h];
        }

        #pragma unroll
        for (int j = 0; j < 8; j++) {
            __stcs(reinterpret_cast<float4*>(ot0 + (size_t)j * PLS), q[j]);
        }
    }
}

extern "C" void kernel_launch(void* const* d_in, const int* in_sizes, int n_in,
                              void* d_out, int out_size) {
    const float* QK    = (const float*)d_in[0];
    const int*   pos   = (const int*)d_in[1];
    const float* table = (const float*)d_in[2];
    float* out = (float*)d_out;

    const int blocks = PN * PL;   // 4096
    gpe_kernel<<<blocks, 256>>>(QK, pos, table, out);
}

// round 11
// speedup vs baseline: 1.0269x; 1.0269x over previous
#include <cuda_runtime.h>
#include <cuda_bf16.h>
#include <cstdint>

// Problem shape (fixed by reference)
#define PN 8
#define PH 32
#define PL 512
#define PS 512
#define PLS (PL * PS)
#define MAXP 100
#define TPAD 33           // pad: bank = (p + h) % 32, p random -> uniform

__global__ __launch_bounds__(256, 5)
void gpe_kernel(const float* __restrict__ QK,
                const int* __restrict__ pos,
                const float* __restrict__ table,
                float* __restrict__ out) {
    __shared__ float t_sh[MAXP * TPAD];  // t_sh[p*33 + h]

    const int bid = blockIdx.x;          // n*PL + l  (one (n,l) row per block)
    const int n = bid >> 9;
    const int l = bid & (PL - 1);
    const int tid = threadIdx.x;

    // Each thread owns one s4 (group of 4 s) and 16 of the 32 heads
    // (strided by 2: spreads the 8-deep bursts across distant DRAM pages).
    const int s4 = tid & 127;
    const int h0 = tid >> 7;             // 0 or 1

    // Issue pos load FIRST so it overlaps the table staging below.
    const int4 pp = __ldg(reinterpret_cast<const int4*>(
        pos + ((size_t)n * PL + l) * PS) + s4);

    // Stage table: 800 float4 covering [100][32] row-major; row 0 zeroed.
    const float4* table4 = reinterpret_cast<const float4*>(table);
    #pragma unroll
    for (int i = tid; i < (MAXP * PH) / 4; i += 256) {
        const int p  = i >> 3;
        const int h4 = (i & 7) << 2;
        float4 v = __ldg(table4 + i);
        if (p == 0) { v.x = 0.f; v.y = 0.f; v.z = 0.f; v.w = 0.f; }
        float* dst = &t_sh[p * TPAD + h4];
        dst[0] = v.x; dst[1] = v.y; dst[2] = v.z; dst[3] = v.w;
    }

    // Gather bases (addr = px + h, pure add in the hot loop)
    const int px = pp.x * TPAD;
    const int py = pp.y * TPAD;
    const int pz = pp.z * TPAD;
    const int pw = pp.w * TPAD;

    __syncthreads();

    const size_t base = ((size_t)n * PH + h0) * (size_t)PLS
                      + (size_t)l * PS + ((size_t)s4 << 2);

    // 8-deep load burst: all 8 h-slots (h = h0 + 2j, j=0..7) in flight,
    // then gather+add, then 8 streaming stores. Two half-rows of 8.
    #pragma unroll
    for (int half = 0; half < 2; half++) {
        const size_t b0 = base + (size_t)(half * 16) * PLS;
        float4 q[8];
        #pragma unroll
        for (int j = 0; j < 8; j++) {
            q[j] = __ldcs(reinterpret_cast<const float4*>(
                QK + b0 + (size_t)(2 * j) * PLS));
        }

        const int hb = h0 + half * 16;
        #pragma unroll
        for (int j = 0; j < 8; j++) {
            const int h = hb + 2 * j;
            q[j].x += t_sh[px + h];
            q[j].y += t_sh[py + h];
            q[j].z += t_sh[pz + h];
            q[j].w += t_sh[pw + h];
        }

        #pragma unroll
        for (int j = 0; j < 8; j++) {
            __stcs(reinterpret_cast<float4*>(
                out + b0 + (size_t)(2 * j) * PLS), q[j]);
        }
    }
}

extern "C" void kernel_launch(void* const* d_in, const int* in_sizes, int n_in,
                              void* d_out, int out_size) {
    const float* QK    = (const float*)d_in[0];
    const int*   pos   = (const int*)d_in[1];
    const float* table = (const float*)d_in[2];
    float* out = (float*)d_out;

    const int blocks = PN * PL;   // 4096
    gpe_kernel<<<blocks, 256>>>(QK, pos, table, out);
}